// round 3
// baseline (speedup 1.0000x reference)
#include <cuda_runtime.h>
#include <math.h>

#define BB   32
#define LL   1024
#define DG   1024
#define HH   1024
#define OUTW (DG + HH)

#define GATE_BLOCKS 128                 // 32 l-tiles x 4 batch-groups
#define COPY_BLOCKS (BB * LL / 2)       // 16384: 2 rows per 512-thread block
#define B_BLOCKS    2048                // persistent grid for kernel B

__device__ float g_gate[BB * LL];

// ---------------------------------------------------------------------------
// Kernel A: mixed.
//   blocks [0, 128):   gate = sigmoid(query @ W + b)   (latency-bound, hidden)
//   blocks [128, ...): out[:, :, 1024:2048] = query[b]  (128 MiB writes, BW-bound)
// 512 threads per block.
// ---------------------------------------------------------------------------
__global__ __launch_bounds__(512, 1)
void kernelA(const float* __restrict__ query,
             const float* __restrict__ W,
             const float* __restrict__ bias,
             float4* __restrict__ out4)
{
    const int bid = blockIdx.x;
    const int tid = threadIdx.x;

    if (bid >= GATE_BLOCKS) {
        // ---- query-broadcast copy: 2 rows per block ----
        const int c   = bid - GATE_BLOCKS;
        const int sub = tid >> 8;            // 0 or 1
        const int t   = tid & 255;           // float4 index within row half
        const int r   = c * 2 + sub;         // (b*LL + l)
        const int b   = r >> 10;
        const float4 q = __ldg((const float4*)query + b * (HH / 4) + t);
        __stcs(&out4[(long long)r * (OUTW / 4) + (DG / 4) + t], q);
        return;
    }

    // ---- gate block ----
    __shared__ float sq[8 * HH];          // 32 KiB: 8 query rows
    __shared__ float red[16][8][32];      // 16 KiB

    const int warp = tid >> 5;
    const int lane = tid & 31;
    const int lt   = bid & 31;            // l-tile 0..31
    const int bg   = bid >> 5;            // batch group 0..3

    {
        const float4* src = (const float4*)(query + bg * 8 * HH);
        float4*       dst = (float4*)sq;
        #pragma unroll
        for (int i = 0; i < 4; ++i)
            dst[tid + i * 512] = src[tid + i * 512];
    }
    __syncthreads();

    const int l = lt * 32 + lane;
    float acc0 = 0.f, acc1 = 0.f, acc2 = 0.f, acc3 = 0.f;
    float acc4 = 0.f, acc5 = 0.f, acc6 = 0.f, acc7 = 0.f;

    const int h0 = warp * 64;
    #pragma unroll
    for (int hb = 0; hb < 64; hb += 8) {
        float w0 = __ldg(&W[(h0 + hb + 0) * LL + l]);
        float w1 = __ldg(&W[(h0 + hb + 1) * LL + l]);
        float w2 = __ldg(&W[(h0 + hb + 2) * LL + l]);
        float w3 = __ldg(&W[(h0 + hb + 3) * LL + l]);
        float w4 = __ldg(&W[(h0 + hb + 4) * LL + l]);
        float w5 = __ldg(&W[(h0 + hb + 5) * LL + l]);
        float w6 = __ldg(&W[(h0 + hb + 6) * LL + l]);
        float w7 = __ldg(&W[(h0 + hb + 7) * LL + l]);

        const float* q = sq + (h0 + hb);
        #pragma unroll
        for (int b = 0; b < 8; ++b) {
            const float* qb = q + b * HH;
            float a = (b==0)?acc0:(b==1)?acc1:(b==2)?acc2:(b==3)?acc3:
                      (b==4)?acc4:(b==5)?acc5:(b==6)?acc6:acc7;
            a = fmaf(qb[0], w0, a);
            a = fmaf(qb[1], w1, a);
            a = fmaf(qb[2], w2, a);
            a = fmaf(qb[3], w3, a);
            a = fmaf(qb[4], w4, a);
            a = fmaf(qb[5], w5, a);
            a = fmaf(qb[6], w6, a);
            a = fmaf(qb[7], w7, a);
            if      (b==0) acc0 = a; else if (b==1) acc1 = a;
            else if (b==2) acc2 = a; else if (b==3) acc3 = a;
            else if (b==4) acc4 = a; else if (b==5) acc5 = a;
            else if (b==6) acc6 = a; else            acc7 = a;
        }
    }

    red[warp][0][lane] = acc0;
    red[warp][1][lane] = acc1;
    red[warp][2][lane] = acc2;
    red[warp][3][lane] = acc3;
    red[warp][4][lane] = acc4;
    red[warp][5][lane] = acc5;
    red[warp][6][lane] = acc6;
    red[warp][7][lane] = acc7;
    __syncthreads();

    if (tid < 256) {
        const int b = tid >> 5;
        float s = 0.f;
        #pragma unroll
        for (int w2 = 0; w2 < 16; ++w2) s += red[w2][b][lane];
        s += __ldg(&bias[l]);
        float g = 1.0f / (1.0f + __expf(-s));
        g_gate[(bg * 8 + b) * LL + l] = g;
    }
}

// ---------------------------------------------------------------------------
// Kernel B: out[:, :, 0:1024] = gate[b,l] * graph[b,l,:]
// Persistent grid-stride over 8.4M float4 elements (8 iters/thread).
// ---------------------------------------------------------------------------
__global__ __launch_bounds__(512, 4)
void kernelB(const float4* __restrict__ graph4,
             float4* __restrict__ out4)
{
    const long long total  = (long long)BB * LL * (DG / 4);   // 8388608
    const long long stride = (long long)B_BLOCKS * 512;

    for (long long i = (long long)blockIdx.x * 512 + threadIdx.x;
         i < total; i += stride) {
        const int row = (int)(i >> 8);          // b*LL + l
        const int t   = (int)(i & 255);
        const float g = __ldg(&g_gate[row]);
        const float4 v = __ldcs(&graph4[i]);
        __stcs(&out4[(long long)row * (OUTW / 4) + t],
               make_float4(v.x * g, v.y * g, v.z * g, v.w * g));
    }
}

extern "C" void kernel_launch(void* const* d_in, const int* in_sizes, int n_in,
                              void* d_out, int out_size)
{
    const float* graph = (const float*)d_in[0];
    const float* query = (const float*)d_in[1];
    const float* W     = (const float*)d_in[2];
    const float* bias  = (const float*)d_in[3];
    float* out = (float*)d_out;

    kernelA<<<GATE_BLOCKS + COPY_BLOCKS, 512>>>(query, W, bias, (float4*)out);
    kernelB<<<B_BLOCKS, 512>>>((const float4*)graph, (float4*)out);

    (void)in_sizes; (void)n_in; (void)out_size;
}

// round 5
// speedup vs baseline: 1.0512x; 1.0512x over previous
#include <cuda_runtime.h>
#include <math.h>

#define BB   32
#define LL   1024
#define DG   1024
#define HH   1024
#define OUTW 2048

#define NBLK   2048            // persistent grid
#define GATEB  128             // gate blocks: 32 l-tiles x 4 batch-groups
#define HALF4  (BB * LL * 256) // 8388608 float4 per output half

__device__ float g_gate[BB * LL];
__device__ int   g_flag;

__global__ void reset_kernel() { g_flag = 0; }

__global__ __launch_bounds__(512, 2)
void fused_kernel(const float4* __restrict__ graph4,
                  const float*  __restrict__ query,
                  const float*  __restrict__ W,
                  const float*  __restrict__ bias,
                  float4* __restrict__ out4)
{
    const int bid = blockIdx.x;
    const int tid = threadIdx.x;

    __shared__ float sq[8 * HH];          // 32 KiB
    __shared__ float red[16][8][32];      // 16 KiB

    if (bid < GATEB) {
        // ---------------- gate: sigmoid(query @ W + b) ----------------
        const int warp = tid >> 5;
        const int lane = tid & 31;
        const int lt   = bid & 31;        // l-tile
        const int bg   = bid >> 5;        // batch group

        {
            const float4* src = (const float4*)(query + bg * 8 * HH);
            float4*       dst = (float4*)sq;
            #pragma unroll
            for (int i = 0; i < 4; ++i)
                dst[tid + i * 512] = src[tid + i * 512];
        }
        __syncthreads();

        const int l = lt * 32 + lane;
        float acc[8];
        #pragma unroll
        for (int b = 0; b < 8; ++b) acc[b] = 0.f;

        const int h0 = warp * 64;
        #pragma unroll
        for (int hb = 0; hb < 64; hb += 8) {
            float w[8];
            #pragma unroll
            for (int j = 0; j < 8; ++j)
                w[j] = __ldg(&W[(h0 + hb + j) * LL + l]);

            const float* q = sq + (h0 + hb);
            #pragma unroll
            for (int b = 0; b < 8; ++b) {
                const float* qb = q + b * HH;
                #pragma unroll
                for (int j = 0; j < 8; ++j)
                    acc[b] = fmaf(qb[j], w[j], acc[b]);
            }
        }

        #pragma unroll
        for (int b = 0; b < 8; ++b) red[warp][b][lane] = acc[b];
        __syncthreads();

        if (tid < 256) {
            const int b = tid >> 5;
            float s = 0.f;
            #pragma unroll
            for (int w2 = 0; w2 < 16; ++w2) s += red[w2][b][lane];
            s += __ldg(&bias[l]);
            float g = 1.0f / (1.0f + __expf(-s));
            g_gate[(bg * 8 + b) * LL + l] = g;
            __threadfence();               // release: gate stores before flag
        }
        __syncthreads();
        if (tid == 0) atomicAdd(&g_flag, 1);
    } else {
        // -------- gate-independent half: out[:,:,1024:2048] = query[b] ------
        const float4* q4 = (const float4*)query;
        const int stride = (NBLK - GATEB) * 512;   // 983040
        for (int i = (bid - GATEB) * 512 + tid; i < HALF4; i += stride) {
            const int row = i >> 8;                // b*LL + l
            const int t   = i & 255;
            const int b   = row >> 10;
            __stcs(&out4[(long long)row * 512 + 256 + t],
                   __ldg(&q4[b * 256 + t]));
        }
    }

    // ---------------- acquire: wait for all 128 gate blocks ----------------
    if (tid == 0) {
        while (*(volatile int*)&g_flag != GATEB) __nanosleep(64);
        __threadfence();                   // acquire before dependent reads
    }
    __syncthreads();

    // -------- scale half: out[:,:,0:1024] = gate[b,l] * graph[b,l,:] -------
    {
        const int stride = NBLK * 512;     // 1048576; exactly 8 iters
        for (int i = bid * 512 + tid; i < HALF4; i += stride) {
            const int row = i >> 8;
            const int t   = i & 255;
            const float g  = __ldg(&g_gate[row]);
            const float4 v = __ldcs(&graph4[i]);
            __stcs(&out4[(long long)row * 512 + t],
                   make_float4(v.x * g, v.y * g, v.z * g, v.w * g));
        }
    }
}

extern "C" void kernel_launch(void* const* d_in, const int* in_sizes, int n_in,
                              void* d_out, int out_size)
{
    const float* graph = (const float*)d_in[0];
    const float* query = (const float*)d_in[1];
    const float* W     = (const float*)d_in[2];
    const float* bias  = (const float*)d_in[3];
    float* out = (float*)d_out;

    reset_kernel<<<1, 1>>>();
    fused_kernel<<<NBLK, 512>>>((const float4*)graph, query, W, bias,
                                (float4*)out);

    (void)in_sizes; (void)n_in; (void)out_size;
}

// round 7
// speedup vs baseline: 1.2741x; 1.2120x over previous
#include <cuda_runtime.h>
#include <math.h>

#define BB   32
#define LL   1024
#define DG   1024
#define HH   1024
#define OUTW 2048

__device__ float g_gate[BB * LL];

// ---------------------------------------------------------------------------
// gate = sigmoid(query @ W + b) — R2's proven kernel (latency-bound, ~10us).
// 128 blocks x 512 threads; runs on a high-priority side stream, fully hidden
// under copy_kernel's 128 MiB of writes.
// ---------------------------------------------------------------------------
__global__ __launch_bounds__(512, 1)
void gate_kernel(const float* __restrict__ query,
                 const float* __restrict__ W,
                 const float* __restrict__ bias)
{
    __shared__ float sq[8 * HH];          // 32 KiB
    __shared__ float red[16][8][32];      // 16 KiB

    const int tid  = threadIdx.x;
    const int warp = tid >> 5;
    const int lane = tid & 31;
    const int lt   = blockIdx.x & 31;     // l-tile
    const int bg   = blockIdx.x >> 5;     // batch group

    {
        const float4* src = (const float4*)(query + bg * 8 * HH);
        float4*       dst = (float4*)sq;
        #pragma unroll
        for (int i = 0; i < 4; ++i)
            dst[tid + i * 512] = src[tid + i * 512];
    }
    __syncthreads();

    const int l = lt * 32 + lane;
    float acc[8];
    #pragma unroll
    for (int b = 0; b < 8; ++b) acc[b] = 0.f;

    const int h0 = warp * 64;
    #pragma unroll
    for (int hb = 0; hb < 64; hb += 8) {
        float w[8];
        #pragma unroll
        for (int j = 0; j < 8; ++j)
            w[j] = __ldg(&W[(h0 + hb + j) * LL + l]);

        const float* q = sq + (h0 + hb);
        #pragma unroll
        for (int b = 0; b < 8; ++b) {
            const float* qb = q + b * HH;
            #pragma unroll
            for (int j = 0; j < 8; ++j)
                acc[b] = fmaf(qb[j], w[j], acc[b]);
        }
    }

    #pragma unroll
    for (int b = 0; b < 8; ++b) red[warp][b][lane] = acc[b];
    __syncthreads();

    if (tid < 256) {
        const int b = tid >> 5;
        float s = 0.f;
        #pragma unroll
        for (int w2 = 0; w2 < 16; ++w2) s += red[w2][b][lane];
        s += __ldg(&bias[l]);
        g_gate[(bg * 8 + b) * LL + l] = 1.0f / (1.0f + __expf(-s));
    }
}

// ---------------------------------------------------------------------------
// copy: out[:, :, 1024:2048] = query[b]   (gate-independent, 128 MiB writes)
// One row per block, 256 threads, float4 coalesced. Lean: no smem, ~16 regs.
// ---------------------------------------------------------------------------
__global__ __launch_bounds__(256, 8)
void copy_kernel(const float4* __restrict__ q4, float4* __restrict__ out4)
{
    const int bl  = blockIdx.x;           // b*LL + l
    const int b   = bl >> 10;
    const int tid = threadIdx.x;
    __stcs(&out4[(long long)bl * (OUTW / 4) + (DG / 4) + tid],
           __ldg(&q4[b * (HH / 4) + tid]));
}

// ---------------------------------------------------------------------------
// scale: out[:, :, 0:1024] = gate[b,l] * graph[b,l,:]   (128R + 128W MiB)
// ---------------------------------------------------------------------------
__global__ __launch_bounds__(256, 8)
void scale_kernel(const float4* __restrict__ graph4, float4* __restrict__ out4)
{
    const int bl  = blockIdx.x;
    const int tid = threadIdx.x;
    const float g  = __ldg(&g_gate[bl]);
    const float4 v = __ldcs(&graph4[(long long)bl * (DG / 4) + tid]);
    __stcs(&out4[(long long)bl * (OUTW / 4) + tid],
           make_float4(v.x * g, v.y * g, v.z * g, v.w * g));
}

extern "C" void kernel_launch(void* const* d_in, const int* in_sizes, int n_in,
                              void* d_out, int out_size)
{
    const float* graph = (const float*)d_in[0];
    const float* query = (const float*)d_in[1];
    const float* W     = (const float*)d_in[2];
    const float* bias  = (const float*)d_in[3];
    float* out = (float*)d_out;

    // One-time stream/event setup (host-side objects only; no device memory).
    static cudaStream_t s_side = nullptr;
    static cudaEvent_t  e_fork = nullptr, e_join = nullptr;
    if (s_side == nullptr) {
        int lo = 0, hi = 0;
        cudaDeviceGetStreamPriorityRange(&lo, &hi);
        cudaStreamCreateWithPriority(&s_side, cudaStreamNonBlocking, hi);
        cudaEventCreateWithFlags(&e_fork, cudaEventDisableTiming);
        cudaEventCreateWithFlags(&e_join, cudaEventDisableTiming);
    }

    // Fork: gate on high-priority side stream, concurrent with copy on main.
    cudaEventRecord(e_fork, 0);
    cudaStreamWaitEvent(s_side, e_fork, 0);

    gate_kernel<<<128, 512, 0, s_side>>>(query, W, bias);
    cudaEventRecord(e_join, s_side);

    copy_kernel<<<BB * LL, 256>>>((const float4*)query, (float4*)out);

    // Join: scale depends on the gate.
    cudaStreamWaitEvent(0, e_join, 0);
    scale_kernel<<<BB * LL, 256>>>((const float4*)graph, (float4*)out);

    (void)in_sizes; (void)n_in; (void)out_size;
}

// round 9
// speedup vs baseline: 1.3260x; 1.0407x over previous
#include <cuda_runtime.h>
#include <math.h>

#define BB   32
#define LL   1024
#define DG   1024
#define HH   1024
#define OUTW 2048
#define BL   (BB * LL)          // 32768 rows

// Split-K partial sums: g_part[hq][b][l], raw (pre-bias, pre-sigmoid)
__device__ float g_part[4 * BL];

// ---------------------------------------------------------------------------
// Stage 1: partial gate GEMM.
// Grid 512 = (32 l-tiles) x (4 batch groups) x (4 h-quarters), 512 threads.
// Each block: 8 batches x 32 l x 256 h partial dot products.
// Warp w covers 16 h; smem stages only the needed 8x256 query slice (8 KiB).
// ---------------------------------------------------------------------------
__global__ __launch_bounds__(512, 1)
void gate_partial(const float* __restrict__ query,
                  const float* __restrict__ W)
{
    __shared__ float sq[8 * 256];         // 8 KiB: 8 batch rows, h-quarter slice
    __shared__ float red[16][8][32];      // 16 KiB

    const int tid  = threadIdx.x;
    const int warp = tid >> 5;            // 0..15
    const int lane = tid & 31;
    const int bid  = blockIdx.x;
    const int lt   = bid & 31;            // l-tile
    const int bg   = (bid >> 5) & 3;      // batch group
    const int hq   = bid >> 7;            // h-quarter

    // Stage 8 x 256 query slice: 512 float4, 1 per thread
    {
        const int b = tid >> 6;           // 0..7
        const int j = tid & 63;           // float4 within 64-f4 slice
        ((float4*)sq)[b * 64 + j] =
            __ldg((const float4*)query + (bg * 8 + b) * (HH / 4) + hq * 64 + j);
    }
    __syncthreads();

    const int l  = lt * 32 + lane;
    const int h0 = hq * 256 + warp * 16;  // global h start for this warp

    float acc[8];
    #pragma unroll
    for (int b = 0; b < 8; ++b) acc[b] = 0.f;

    #pragma unroll
    for (int g2 = 0; g2 < 2; ++g2) {
        float w[8];
        #pragma unroll
        for (int j = 0; j < 8; ++j)
            w[j] = __ldg(&W[(h0 + g2 * 8 + j) * LL + l]);

        const float* q = sq + warp * 16 + g2 * 8;   // local h offset
        #pragma unroll
        for (int b = 0; b < 8; ++b) {
            const float* qb = q + b * 256;
            #pragma unroll
            for (int j = 0; j < 8; ++j)
                acc[b] = fmaf(qb[j], w[j], acc[b]);
        }
    }

    #pragma unroll
    for (int b = 0; b < 8; ++b) red[warp][b][lane] = acc[b];
    __syncthreads();

    if (tid < 256) {
        const int b = tid >> 5;
        float s = 0.f;
        #pragma unroll
        for (int w2 = 0; w2 < 16; ++w2) s += red[w2][b][lane];
        g_part[hq * BL + (bg * 8 + b) * LL + l] = s;
    }
}

// ---------------------------------------------------------------------------
// Stage 2: stream with fused gate finalize.
// One block per (b,l) row, 256 threads (R2's proven 56.6us form).
// Thread 0: g = sigmoid(sum of 4 partials + bias), broadcast via smem.
// Graph/query loads are issued BEFORE the barrier to hide the finalize.
// ---------------------------------------------------------------------------
__global__ __launch_bounds__(256, 8)
void stream_kernel(const float4* __restrict__ graph4,
                   const float4* __restrict__ query4,
                   const float*  __restrict__ bias,
                   float4* __restrict__ out4)
{
    __shared__ float sg;

    const int bl  = blockIdx.x;           // b*LL + l
    const int b   = bl >> 10;
    const int l   = bl & 1023;
    const int tid = threadIdx.x;

    // Issue the long-latency loads first (independent of the gate)
    const float4 v = __ldcs(&graph4[(long long)bl * (DG / 4) + tid]);
    const float4 q = __ldg(&query4[b * (HH / 4) + tid]);

    if (tid == 0) {
        float s = __ldg(&bias[l])
                + __ldg(&g_part[0 * BL + bl])
                + __ldg(&g_part[1 * BL + bl])
                + __ldg(&g_part[2 * BL + bl])
                + __ldg(&g_part[3 * BL + bl]);
        sg = 1.0f / (1.0f + __expf(-s));
    }
    __syncthreads();
    const float g = sg;

    float4* o = out4 + (long long)bl * (OUTW / 4);
    __stcs(&o[tid],            make_float4(v.x * g, v.y * g, v.z * g, v.w * g));
    __stcs(&o[(DG / 4) + tid], q);
}

extern "C" void kernel_launch(void* const* d_in, const int* in_sizes, int n_in,
                              void* d_out, int out_size)
{
    const float* graph = (const float*)d_in[0];
    const float* query = (const float*)d_in[1];
    const float* W     = (const float*)d_in[2];
    const float* bias  = (const float*)d_in[3];
    float* out = (float*)d_out;

    gate_partial<<<512, 512>>>(query, W);
    stream_kernel<<<BL, 256>>>((const float4*)graph,
                               (const float4*)query,
                               bias,
                               (float4*)out);

    (void)in_sizes; (void)n_in; (void)out_size;
}